// round 6
// baseline (speedup 1.0000x reference)
#include <cuda_runtime.h>

// ---------------------------------------------------------------------------
// 256-bin histogram of 33.5M fp32 in [0,255] + count = batchsize*hist[0].
//
// R6: software-pipelined loads (2-deep ping-pong, 4x LDG.128 per stage kept
// continuously in flight) to fix the demand-side DRAM gap (48.5% busy);
// 7 blocks/SM (28 warps). u8 per-thread-column counters, batch-8 collision-
// corrected increments, fused last-block finalize.
// ---------------------------------------------------------------------------

#define TPB        128
#define SBINS      257                      // 256 bins + spill slot
#define WPB        32                       // 32-bit words per bin (128 u8 cols)
#define SMEM_WORDS (SBINS * WPB)            // 32896 bytes
#define NBLK       1064                     // 152 SMs * 7 -> one wave

__device__ unsigned int g_hist[256];
__device__ unsigned int g_done;

#define BINC   1.00392156862745f            /* 256/255 */
#define FBIAS  8388608.0f                   /* 2^23 */

__device__ __forceinline__ unsigned binof(float x) {
    float f = __fmaf_rz(x, BINC, FBIAS);    // mantissa trick, no CVT
    unsigned b = __float_as_uint(f) & 1023u;
    return b > 256u ? 256u : b;             // clamp into spill
}

// 8 elements of one lane: 8 batched LDS.U8, exact pairwise collision
// correction overlapped with LDS latency, 8 ordered STS.U8.
__device__ __forceinline__ void acc8(unsigned char* sh8, unsigned lanoff,
                                     float4 u, float4 v) {
    unsigned b[8], a[8], c[8];
    b[0] = binof(u.x); b[1] = binof(u.y); b[2] = binof(u.z); b[3] = binof(u.w);
    b[4] = binof(v.x); b[5] = binof(v.y); b[6] = binof(v.z); b[7] = binof(v.w);
    #pragma unroll
    for (int i = 0; i < 8; i++) { a[i] = b[i] * 128 + lanoff; c[i] = sh8[a[i]]; }
    #pragma unroll
    for (int i = 0; i < 8; i++) {
        unsigned inc = 1u;
        #pragma unroll
        for (int j = 0; j < i; j++) inc += (b[i] == b[j]);
        c[i] += inc;
    }
    #pragma unroll
    for (int i = 0; i < 8; i++) sh8[a[i]] = (unsigned char)c[i];
}

#define LOAD4(dst, idx) do {                     \
    dst[0] = in4[(idx)];                         \
    dst[1] = in4[(idx) + S];                     \
    dst[2] = in4[(idx) + 2 * S];                 \
    dst[3] = in4[(idx) + 3 * S];                 \
} while (0)

__global__ void __launch_bounds__(TPB, 7)
hist_kernel(const float* __restrict__ inf, const int* __restrict__ bsz,
            float* __restrict__ out, int n) {
    __shared__ unsigned int sh[SMEM_WORDS];
    const int t = threadIdx.x;

    #pragma unroll 4
    for (int i = t; i < SMEM_WORDS; i += TPB) sh[i] = 0u;
    __syncthreads();

    unsigned char* sh8 = (unsigned char*)sh;
    const unsigned lanoff = ((t & 31) << 2) | (t >> 5);

    const int n4 = n >> 2;
    const float4* __restrict__ in4 = (const float4*)inf;
    const int S = gridDim.x * TPB;
    int i = blockIdx.x * TPB + t;

    // ---- 2-deep pipelined main loop: one 4xfloat4 stage in flight while
    //      the previous stage's 16 elements are accumulated. ----
    float4 v[4], w[4];
    if (i + 3 * S < n4) {
        LOAD4(v, i);
        i += 4 * S;
        while (i + 3 * S < n4) {
            LOAD4(w, i);                       // prefetch B
            acc8(sh8, lanoff, v[0], v[1]);     // process A (B in flight)
            acc8(sh8, lanoff, v[2], v[3]);
            i += 4 * S;
            if (i + 3 * S < n4) {
                LOAD4(v, i);                   // prefetch A'
                acc8(sh8, lanoff, w[0], w[1]); // process B (A' in flight)
                acc8(sh8, lanoff, w[2], w[3]);
                i += 4 * S;
            } else {
                acc8(sh8, lanoff, w[0], w[1]);
                acc8(sh8, lanoff, w[2], w[3]);
                goto remainder;
            }
        }
        acc8(sh8, lanoff, v[0], v[1]);         // drain pending stage
        acc8(sh8, lanoff, v[2], v[3]);
    }
remainder:
    for (; i < n4; i += S) {
        float4 x = in4[i];
        unsigned b0 = binof(x.x), b1 = binof(x.y), b2 = binof(x.z), b3 = binof(x.w);
        unsigned a0 = b0 * 128 + lanoff, a1 = b1 * 128 + lanoff;
        unsigned a2 = b2 * 128 + lanoff, a3 = b3 * 128 + lanoff;
        unsigned c0 = sh8[a0], c1 = sh8[a1], c2 = sh8[a2], c3 = sh8[a3];
        c0 += 1u;
        c1 += 1u + (b1 == b0);
        c2 += 1u + (b2 == b0) + (b2 == b1);
        c3 += 1u + (b3 == b0) + (b3 == b1) + (b3 == b2);
        sh8[a0] = (unsigned char)c0; sh8[a1] = (unsigned char)c1;
        sh8[a2] = (unsigned char)c2; sh8[a3] = (unsigned char)c3;
    }
    if (blockIdx.x == 0 && t < (n & 3)) {      // scalar tail
        unsigned a = binof(inf[(n4 << 2) + t]) * 128 + lanoff;
        sh8[a] = (unsigned char)(sh8[a] + 1);
    }
    __syncthreads();

    // per-bin byte-sum via dp4a; one global atomic per bin per block
    for (int b = t; b < 256; b += TPB) {
        unsigned int s = 0;
        #pragma unroll 8
        for (int k = 0; k < WPB; k++)
            s = __dp4a(sh[b * WPB + ((k + t) & (WPB - 1))], 0x01010101u, s);
        atomicAdd(&g_hist[b], s);
    }

    // last arriving block finalizes and resets state (idempotent replays)
    __shared__ unsigned int is_last;
    __shared__ float h0s;
    __threadfence();
    if (t == 0) {
        unsigned ticket = atomicAdd(&g_done, 1u);
        is_last = (ticket == (unsigned)(gridDim.x - 1));
    }
    __syncthreads();
    if (is_last) {
        __threadfence();                        // acquire histogram atomics
        if (t == 0) { h0s = (float)g_hist[0]; g_done = 0u; }
        __syncthreads();
        float c = (float)(*bsz) * h0s;
        #pragma unroll
        for (int b = t; b < 256; b += TPB) {
            out[b]       = (float)g_hist[b];
            out[256 + b] = c;
        }
        __syncthreads();
        #pragma unroll
        for (int b = t; b < 256; b += TPB) g_hist[b] = 0u;  // reset after reads
    }
}

extern "C" void kernel_launch(void* const* d_in, const int* in_sizes, int n_in,
                              void* d_out, int out_size) {
    const float* x;
    const int*   bs;
    int n;
    if (n_in >= 2 && in_sizes[0] >= in_sizes[1]) {
        x = (const float*)d_in[0]; bs = (const int*)d_in[1]; n = in_sizes[0];
    } else {
        x = (const float*)d_in[1]; bs = (const int*)d_in[0]; n = in_sizes[1];
    }
    hist_kernel<<<NBLK, TPB>>>(x, bs, (float*)d_out, n);
}